// round 2
// baseline (speedup 1.0000x reference)
#include <cuda_runtime.h>
#include <math.h>

#ifndef M_PI
#define M_PI 3.14159265358979323846
#endif

// ---------------- dims ----------------
#define EDIM 128
#define HID 256
#define CINCH 26
#define COUTCH 26
#define NLAT 361
#define NLONF 720
#define TSM 90
#define NLONS 180
#define LMAXD 90
#define MMAXD 91
#define M2 182            // 2*MMAX (re,im rows)
#define PFULL (NLAT*NLONF)   // 259920
#define PSMALL (TSM*NLONS)   // 16200
#define NBLK 4

// ---------------- device scratch ----------------
__device__ float g_Pw_full[LMAXD*MMAXD*NLAT];
__device__ float g_Pinv_full[MMAXD*NLAT*LMAXD];
__device__ float g_Pw_small[LMAXD*MMAXD*TSM];
__device__ float g_Pinv_small[MMAXD*TSM*LMAXD];
__device__ float g_Tf_full[M2*NLONF];
__device__ float g_Ti_full[NLONF*M2];
__device__ float g_Tf_small[M2*NLONS];
__device__ float g_Ti_small[NLONS*M2];
__device__ float g_Wbig[NBLK*LMAXD*256*256];
__device__ float g_wT_enc0[CINCH*EDIM];
__device__ float g_wT_enc1[EDIM*EDIM];
__device__ float g_wT_mlp1[NBLK*EDIM*HID];
__device__ float g_wT_mlp2[NBLK*HID*EDIM];
__device__ float g_wT_skip[NBLK*EDIM*EDIM];
__device__ float g_wT_dec0[(EDIM+CINCH)*EDIM];
__device__ float g_wT_dec1[EDIM*COUTCH];
__device__ float g_xin[PFULL*CINCH];
__device__ float g_bufA[PFULL*EDIM];
__device__ float g_bufB[PFULL*EDIM];
__device__ float g_bufC[PFULL*EDIM];
__device__ float g_bufD[PFULL*EDIM];
__device__ float g_bufE[PSMALL*EDIM];
__device__ float g_bufH[PFULL*HID];
__device__ float g_G1[NLAT*M2*EDIM];
__device__ float g_G2[NLAT*M2*EDIM];
__device__ float g_cA[LMAXD*MMAXD*2*EDIM];
__device__ float g_cB[LMAXD*MMAXD*2*EDIM];
__device__ float g_stats[2*EDIM];
__device__ float g_murs[2*EDIM];

__device__ __forceinline__ float gelu_f(float x){
    return 0.5f*x*(1.0f+erff(x*0.7071067811865475f));
}

// ---------------- setup kernels ----------------
// Associated Legendre (orthonormal, as in reference), computed in fp64 per theta.
__global__ void legendre_k(float* __restrict__ Pw, float* __restrict__ Pinv, int T){
    int t = blockIdx.x*blockDim.x + threadIdx.x;
    if (t >= T) return;
    double theta = M_PI*((double)t + 0.5)/(double)T;
    double ct = cos(theta), st = sin(theta);
    double w = (M_PI/(double)T)*st;
    double diag = sqrt(1.0/(4.0*M_PI));  // p[0][0]
    for (int m = 0; m < MMAXD; m++){
        if (m > 0){
            if (m < LMAXD) diag = sqrt((2.0*m+1.0)/(2.0*m))*st*diag;
            else diag = 0.0;
        }
        double pl1 = 0.0, pl2 = 0.0;
        for (int l = 0; l < LMAXD; l++){
            double v;
            if (m >= LMAXD || l < m) v = 0.0;
            else if (l == m) v = diag;
            else if (l == m+1) v = sqrt(2.0*m+3.0)*ct*diag;
            else {
                double dl = (double)l, dm = (double)m;
                double a = sqrt((4.0*dl*dl-1.0)/(dl*dl-dm*dm));
                double b = sqrt(((dl-1.0)*(dl-1.0)-dm*dm)/(4.0*(dl-1.0)*(dl-1.0)-1.0));
                v = a*(ct*pl1 - b*pl2);
            }
            pl2 = pl1; pl1 = v;
            Pw[((long long)l*MMAXD + m)*T + t]   = (float)(v*w);
            Pinv[((long long)m*T + t)*LMAXD + l] = (float)v;
        }
    }
}

// DFT tables. Forward: F[m] = (2pi/n) * sum_j x_j e^{-i 2pi m j/n}.
// Inverse (irfft norm='forward'): x_j = Re(g0) + 2*sum_{m>=1}(Re g cos - Im g sin),
// Nyquist (n=180,m=90): factor 1, imag ignored.
__global__ void fft_tables_k(float* __restrict__ Tf, float* __restrict__ Ti, int n){
    int idx = blockIdx.x*blockDim.x + threadIdx.x;
    if (idx >= MMAXD*n) return;
    int m = idx / n, j = idx % n;
    double ang = (2.0*M_PI*(double)m*(double)j)/(double)n;
    double s, c;
    sincos(ang, &s, &c);
    double sc = 2.0*M_PI/(double)n;
    Tf[(2*m)*n + j]   = (float)(c*sc);
    Tf[(2*m+1)*n + j] = (float)(-s*sc);
    bool nyq = (2*m == n);
    double am = (m == 0 || nyq) ? 1.0 : 2.0;
    Ti[(long long)j*M2 + 2*m]   = (float)(am*c);
    Ti[(long long)j*M2 + 2*m+1] = (m == 0 || nyq) ? 0.0f : (float)(-2.0*s);
}

// Generic transpose: in [R][C] -> out [C][R]
__global__ void transpose_k(const float* __restrict__ in, float* __restrict__ out, int R, int C){
    long long idx = (long long)blockIdx.x*blockDim.x + threadIdx.x;
    if (idx >= (long long)R*C) return;
    int c = (int)(idx % C);
    long long r = idx / C;
    out[(long long)c*R + r] = in[idx];
}

// Complex weight embedding: per (b,l) a 256x256 real matrix [[Wr,Wi],[-Wi,Wr]]
__global__ void build_wbig_k(const float* __restrict__ wr, const float* __restrict__ wi,
                             float* __restrict__ W){
    long long idx = (long long)blockIdx.x*blockDim.x + threadIdx.x;
    if (idx >= (long long)NBLK*EDIM*EDIM*LMAXD) return;
    int l = (int)(idx % LMAXD); long long r = idx / LMAXD;
    int i = (int)(r % EDIM); r /= EDIM;
    int o = (int)(r % EDIM); int b = (int)(r / EDIM);
    float vr = wr[idx], vi = wi[idx];   // layout [b][o][i][l]
    float* M = W + ((long long)b*LMAXD + l)*65536;
    M[(long long)i*256 + o]             = vr;
    M[(long long)i*256 + 128 + o]       = vi;
    M[(long long)(128+i)*256 + o]       = -vi;
    M[(long long)(128+i)*256 + 128 + o] = vr;
}

__global__ void concat_k(const float* __restrict__ xe, const float* __restrict__ xin,
                         float* __restrict__ out){
    long long idx = (long long)blockIdx.x*blockDim.x + threadIdx.x;
    if (idx >= (long long)PFULL*(EDIM+CINCH)) return;
    long long p = idx / (EDIM+CINCH);
    int c = (int)(idx % (EDIM+CINCH));
    out[idx] = (c < EDIM) ? xe[p*EDIM + c] : xin[p*CINCH + (c-EDIM)];
}

__global__ void zero_k(float* p, int n){
    int i = blockIdx.x*blockDim.x + threadIdx.x;
    if (i < n) p[i] = 0.0f;
}

// ---------------- instance norm ----------------
__global__ void inorm_reduce_k(const float* __restrict__ x, int P, float* __restrict__ stats){
    int ch = threadIdx.x;
    float s = 0.f, q = 0.f;
    for (int r = blockIdx.x; r < P; r += gridDim.x){
        float v = x[(long long)r*EDIM + ch];
        s += v; q += v*v;
    }
    atomicAdd(&stats[ch], s);
    atomicAdd(&stats[EDIM+ch], q);
}
__global__ void inorm_fin_k(const float* __restrict__ stats, float* __restrict__ murs, float invP){
    int ch = threadIdx.x;
    float mu = stats[ch]*invP;
    float var = stats[EDIM+ch]*invP - mu*mu;
    murs[ch] = mu;
    murs[EDIM+ch] = rsqrtf(var + 1e-6f);
}
__global__ void inorm_apply_k(const float* __restrict__ x, float* __restrict__ y,
                              const float* __restrict__ murs,
                              const float* __restrict__ g, const float* __restrict__ b,
                              long long total, int act){
    long long idx = (long long)blockIdx.x*blockDim.x + threadIdx.x;
    if (idx >= total) return;
    int ch = (int)(idx & (EDIM-1));
    float v = (x[idx] - murs[ch])*murs[EDIM+ch]*g[ch] + b[ch];
    if (act) v = gelu_f(v);
    y[idx] = v;
}

// ---------------- generic batched GEMM ----------------
// C = act(A@B + bias) + add ; row-major with lda/ldb/ldc, per-batch element strides.
#define BM 64
#define BN 64
#define BKK 16
__global__ void gemm_k(const float* __restrict__ A, const float* __restrict__ B,
                       float* __restrict__ C,
                       const float* __restrict__ bias, const float* __restrict__ addp,
                       int M, int N, int K, int lda, int ldb, int ldc,
                       long long sA, long long sB, long long sC, int act){
    __shared__ float As[BKK][BM];
    __shared__ float Bs[BKK][BN];
    long long z = blockIdx.z;
    A += z*sA; B += z*sB; C += z*sC;
    if (addp) addp += z*sC;
    int m0 = blockIdx.y*BM, n0 = blockIdx.x*BN;
    int tid = threadIdx.x;
    int ty = tid >> 4, tx = tid & 15;
    float acc[4][4] = {};
    for (int k0 = 0; k0 < K; k0 += BKK){
        {
            int j = tid & 15, ib = tid >> 4;
            #pragma unroll
            for (int s = 0; s < 4; s++){
                int i = ib + s*16;
                int m = m0 + i, k = k0 + j;
                As[j][i] = (m < M && k < K) ? A[(long long)m*lda + k] : 0.f;
            }
            int n = tid & 63, kb = tid >> 6;
            #pragma unroll
            for (int s = 0; s < 4; s++){
                int k = kb + s*4;
                int kk = k0 + k, nn = n0 + n;
                Bs[k][n] = (kk < K && nn < N) ? B[(long long)kk*ldb + nn] : 0.f;
            }
        }
        __syncthreads();
        #pragma unroll
        for (int k = 0; k < BKK; k++){
            float a[4], b[4];
            #pragma unroll
            for (int r = 0; r < 4; r++) a[r] = As[k][ty*4+r];
            #pragma unroll
            for (int c = 0; c < 4; c++) b[c] = Bs[k][tx*4+c];
            #pragma unroll
            for (int r = 0; r < 4; r++)
                #pragma unroll
                for (int c = 0; c < 4; c++)
                    acc[r][c] += a[r]*b[c];
        }
        __syncthreads();
    }
    #pragma unroll
    for (int r = 0; r < 4; r++){
        int m = m0 + ty*4 + r; if (m >= M) continue;
        #pragma unroll
        for (int c = 0; c < 4; c++){
            int n = n0 + tx*4 + c; if (n >= N) continue;
            float v = acc[r][c];
            if (bias) v += bias[n];
            if (act == 1) v = gelu_f(v);
            if (addp) v += addp[(long long)m*ldc + n];
            C[(long long)m*ldc + n] = v;
        }
    }
}

// ---------------- host helpers ----------------
static void launch_gemm(const float* A, const float* B, float* C,
                        const float* bias, const float* addp,
                        int M, int N, int K, int lda, int ldb, int ldc,
                        long long sA, long long sB, long long sC, int batch, int act){
    dim3 grid((N+BN-1)/BN, (M+BM-1)/BM, batch);
    gemm_k<<<grid, 256>>>(A, B, C, bias, addp, M, N, K, lda, ldb, ldc, sA, sB, sC, act);
}

#define SYMP(var, sym) do { void* _t = nullptr; cudaGetSymbolAddress(&_t, sym); var = (float*)_t; } while(0)

static void inorm_seq(const float* x, float* y, const float* g, const float* b,
                      int P, int act, float* stats, float* murs){
    zero_k<<<1, 256>>>(stats, 2*EDIM);
    inorm_reduce_k<<<256, EDIM>>>(x, P, stats);
    inorm_fin_k<<<1, EDIM>>>(stats, murs, 1.0f/(float)P);
    long long tot = (long long)P*EDIM;
    inorm_apply_k<<<(unsigned)((tot+255)/256), 256>>>(x, y, murs, g, b, tot, act);
}

extern "C" void kernel_launch(void* const* d_in, const int* in_sizes, int n_in,
                              void* d_out, int out_size){
    const float* x_in    = (const float*)d_in[0];
    const float* w_enc0  = (const float*)d_in[1];
    const float* b_enc0  = (const float*)d_in[2];
    const float* w_enc1  = (const float*)d_in[3];
    const float* w_specr = (const float*)d_in[4];
    const float* w_speci = (const float*)d_in[5];
    const float* g0      = (const float*)d_in[6];
    const float* b0      = (const float*)d_in[7];
    const float* g1      = (const float*)d_in[8];
    const float* b1      = (const float*)d_in[9];
    const float* w_mlp1  = (const float*)d_in[10];
    const float* b_mlp1  = (const float*)d_in[11];
    const float* w_mlp2  = (const float*)d_in[12];
    const float* b_mlp2  = (const float*)d_in[13];
    const float* w_skip  = (const float*)d_in[14];
    const float* w_dec0  = (const float*)d_in[15];
    const float* b_dec0  = (const float*)d_in[16];
    const float* w_dec1  = (const float*)d_in[17];
    float* out = (float*)d_out;

    float *Pwf,*Pif,*Pws,*Pis,*Tff,*Tif,*Tfs,*Tis,*Wbig;
    float *wTe0,*wTe1,*wTm1,*wTm2,*wTsk,*wTd0,*wTd1;
    float *xin,*bufA,*bufB,*bufC,*bufD,*bufE,*bufH,*G1,*G2,*cA,*cB,*stats,*murs;
    SYMP(Pwf, g_Pw_full);  SYMP(Pif, g_Pinv_full);
    SYMP(Pws, g_Pw_small); SYMP(Pis, g_Pinv_small);
    SYMP(Tff, g_Tf_full);  SYMP(Tif, g_Ti_full);
    SYMP(Tfs, g_Tf_small); SYMP(Tis, g_Ti_small);
    SYMP(Wbig, g_Wbig);
    SYMP(wTe0, g_wT_enc0); SYMP(wTe1, g_wT_enc1);
    SYMP(wTm1, g_wT_mlp1); SYMP(wTm2, g_wT_mlp2); SYMP(wTsk, g_wT_skip);
    SYMP(wTd0, g_wT_dec0); SYMP(wTd1, g_wT_dec1);
    SYMP(xin, g_xin);
    SYMP(bufA, g_bufA); SYMP(bufB, g_bufB); SYMP(bufC, g_bufC);
    SYMP(bufD, g_bufD); SYMP(bufE, g_bufE); SYMP(bufH, g_bufH);
    SYMP(G1, g_G1); SYMP(G2, g_G2); SYMP(cA, g_cA); SYMP(cB, g_cB);
    SYMP(stats, g_stats); SYMP(murs, g_murs);

    // ---- setup: tables + weight transposes (cheap, in-graph) ----
    legendre_k<<<(NLAT+63)/64, 64>>>(Pwf, Pif, NLAT);
    legendre_k<<<(TSM+63)/64, 64>>>(Pws, Pis, TSM);
    fft_tables_k<<<(MMAXD*NLONF+255)/256, 256>>>(Tff, Tif, NLONF);
    fft_tables_k<<<(MMAXD*NLONS+255)/256, 256>>>(Tfs, Tis, NLONS);
    transpose_k<<<(EDIM*CINCH+255)/256, 256>>>(w_enc0, wTe0, EDIM, CINCH);
    transpose_k<<<(EDIM*EDIM+255)/256, 256>>>(w_enc1, wTe1, EDIM, EDIM);
    for (int i = 0; i < NBLK; i++){
        transpose_k<<<(HID*EDIM+255)/256, 256>>>(w_mlp1 + (long long)i*HID*EDIM, wTm1 + (long long)i*EDIM*HID, HID, EDIM);
        transpose_k<<<(EDIM*HID+255)/256, 256>>>(w_mlp2 + (long long)i*EDIM*HID, wTm2 + (long long)i*HID*EDIM, EDIM, HID);
        transpose_k<<<(EDIM*EDIM+255)/256, 256>>>(w_skip + (long long)i*EDIM*EDIM, wTsk + (long long)i*EDIM*EDIM, EDIM, EDIM);
    }
    transpose_k<<<(EDIM*(EDIM+CINCH)+255)/256, 256>>>(w_dec0, wTd0, EDIM, EDIM+CINCH);
    transpose_k<<<(COUTCH*EDIM+255)/256, 256>>>(w_dec1, wTd1, COUTCH, EDIM);
    build_wbig_k<<<(unsigned)(((long long)NBLK*EDIM*EDIM*LMAXD + 255)/256), 256>>>(w_specr, w_speci, Wbig);
    transpose_k<<<(unsigned)(((long long)CINCH*PFULL + 255)/256), 256>>>(x_in, xin, CINCH, PFULL);

    // ---- encoder: bufA = enc1 @ gelu(enc0 @ x + b) ----
    launch_gemm(xin,  wTe0, bufC, b_enc0, nullptr, PFULL, EDIM, CINCH, CINCH, EDIM, EDIM, 0,0,0, 1, 1);
    launch_gemm(bufC, wTe1, bufA, nullptr, nullptr, PFULL, EDIM, EDIM, EDIM, EDIM, EDIM, 0,0,0, 1, 0);

    // ---- blocks ----
    struct Blk { int Tin, nlin, Tout, nlout; bool sres; };
    const Blk blks[NBLK] = {
        {NLAT, NLONF, TSM, NLONS, true},
        {TSM, NLONS, TSM, NLONS, false},
        {TSM, NLONS, TSM, NLONS, false},
        {TSM, NLONS, NLAT, NLONF, true},
    };
    float* infld[NBLK]  = {bufA, bufA, bufE, bufA};
    float* outfld[NBLK] = {bufA, bufE, bufA, bufB};

    for (int i = 0; i < NBLK; i++){
        const Blk& bk = blks[i];
        const float* Tf_in  = (bk.nlin == NLONF) ? Tff : Tfs;
        const float* Pw_in  = (bk.Tin == NLAT) ? Pwf : Pws;
        const float* Pi_out = (bk.Tout == NLAT) ? Pif : Pis;
        const float* Ti_out = (bk.nlout == NLONF) ? Tif : Tis;
        int Pout = bk.Tout * bk.nlout;
        float* in = infld[i];
        float* xout = outfld[i];

        // forward rFFT: G1[t][m2][ch] (batch over t)
        launch_gemm(Tf_in, in, G1, nullptr, nullptr,
                    M2, EDIM, bk.nlin, bk.nlin, EDIM, EDIM,
                    0, (long long)bk.nlin*EDIM, (long long)M2*EDIM, bk.Tin, 0);
        // Legendre analysis: cA[l][m2][ch] (batch over m)
        launch_gemm(Pw_in, G1, cA, nullptr, nullptr,
                    LMAXD, 256, bk.Tin, MMAXD*bk.Tin, M2*EDIM, MMAXD*256,
                    bk.Tin, 256, 256, MMAXD, 0);
        // spectral conv (batch over l): cB = cA @ Wbig_l
        launch_gemm(cA, Wbig + (long long)i*LMAXD*65536, cB, nullptr, nullptr,
                    MMAXD, 256, 256, 256, 256, 256,
                    (long long)MMAXD*256, 65536, (long long)MMAXD*256, LMAXD, 0);
        // Legendre synthesis (spec path): G1[t][m2][ch] (batch over m)
        launch_gemm(Pi_out, cB, G1, nullptr, nullptr,
                    bk.Tout, 256, LMAXD, LMAXD, MMAXD*256, M2*EDIM,
                    (long long)bk.Tout*LMAXD, 256, 256, MMAXD, 0);
        // inverse rFFT: xf -> bufB (batch over t)
        launch_gemm(Ti_out, G1, bufB, nullptr, nullptr,
                    bk.nlout, EDIM, M2, M2, EDIM, EDIM,
                    0, (long long)M2*EDIM, (long long)bk.nlout*EDIM, bk.Tout, 0);

        // residual
        const float* res;
        if (bk.sres){
            launch_gemm(Pi_out, cA, G2, nullptr, nullptr,
                        bk.Tout, 256, LMAXD, LMAXD, MMAXD*256, M2*EDIM,
                        (long long)bk.Tout*LMAXD, 256, 256, MMAXD, 0);
            launch_gemm(Ti_out, G2, bufC, nullptr, nullptr,
                        bk.nlout, EDIM, M2, M2, EDIM, EDIM,
                        0, (long long)M2*EDIM, (long long)bk.nlout*EDIM, bk.Tout, 0);
            res = bufC;
        } else {
            res = in;
        }

        // norm0 + gelu -> bufD
        inorm_seq(bufB, bufD, g0 + (long long)i*EDIM, b0 + (long long)i*EDIM, Pout, 1, stats, murs);
        // MLP: bufH = gelu(bufD @ W1 + b1) ; bufB = bufH @ W2 + b2
        launch_gemm(bufD, wTm1 + (long long)i*EDIM*HID, bufH, b_mlp1 + (long long)i*HID, nullptr,
                    Pout, HID, EDIM, EDIM, HID, HID, 0,0,0, 1, 1);
        launch_gemm(bufH, wTm2 + (long long)i*HID*EDIM, bufB, b_mlp2 + (long long)i*EDIM, nullptr,
                    Pout, EDIM, HID, HID, EDIM, EDIM, 0,0,0, 1, 0);
        // norm1 -> bufD
        inorm_seq(bufB, bufD, g1 + (long long)i*EDIM, b1 + (long long)i*EDIM, Pout, 0, stats, murs);
        // x_next = bufD + res @ w_skip
        launch_gemm(res, wTsk + (long long)i*EDIM*EDIM, xout, nullptr, bufD,
                    Pout, EDIM, EDIM, EDIM, EDIM, EDIM, 0,0,0, 1, 0);
    }

    // ---- decoder ----
    concat_k<<<(unsigned)(((long long)PFULL*(EDIM+CINCH) + 255)/256), 256>>>(bufB, xin, bufH);
    launch_gemm(bufH, wTd0, bufA, b_dec0, nullptr,
                PFULL, EDIM, EDIM+CINCH, EDIM+CINCH, EDIM, EDIM, 0,0,0, 1, 1);
    launch_gemm(bufA, wTd1, bufC, nullptr, nullptr,
                PFULL, COUTCH, EDIM, EDIM, COUTCH, COUTCH, 0,0,0, 1, 0);
    // [P][26] -> [26][P]
    transpose_k<<<(unsigned)(((long long)PFULL*COUTCH + 255)/256), 256>>>(bufC, out, PFULL, COUTCH);
}

// round 3
// speedup vs baseline: 1.0157x; 1.0157x over previous
#include <cuda_runtime.h>
#include <math.h>

#ifndef M_PI
#define M_PI 3.14159265358979323846
#endif

// ---------------- dims ----------------
#define EDIM 128
#define HID 256
#define CINCH 26
#define COUTCH 26
#define NLAT 361
#define NLONF 720
#define TSM 90
#define NLONS 180
#define LMAXD 90
#define MMAXD 91
#define M2 182            // 2*MMAX (re,im rows)
#define PFULL (NLAT*NLONF)   // 259920
#define PSMALL (TSM*NLONS)   // 16200
#define NBLK 4

// ---------------- device scratch ----------------
__device__ float g_Pw_full[LMAXD*MMAXD*NLAT];
__device__ float g_Pinv_full[MMAXD*NLAT*LMAXD];
__device__ float g_Pw_small[LMAXD*MMAXD*TSM];
__device__ float g_Pinv_small[MMAXD*TSM*LMAXD];
__device__ float g_Tf_full[M2*NLONF];
__device__ float g_Ti_full[NLONF*M2];
__device__ float g_Tf_small[M2*NLONS];
__device__ float g_Ti_small[NLONS*M2];
__device__ float g_Wbig[NBLK*LMAXD*256*256];
__device__ float g_wT_enc0[CINCH*EDIM];
__device__ float g_wT_enc1[EDIM*EDIM];
__device__ float g_wT_mlp1[NBLK*EDIM*HID];
__device__ float g_wT_mlp2[NBLK*HID*EDIM];
__device__ float g_wT_skip[NBLK*EDIM*EDIM];
__device__ float g_wT_dec0[(EDIM+CINCH)*EDIM];
__device__ float g_wT_dec1[EDIM*COUTCH];
__device__ float g_xin[PFULL*CINCH];
__device__ float g_bufA[PFULL*EDIM];
__device__ float g_bufB[PFULL*EDIM];
__device__ float g_bufC[PFULL*EDIM];
__device__ float g_bufD[PFULL*EDIM];
__device__ float g_bufE[PSMALL*EDIM];
__device__ float g_bufH[PFULL*HID];
__device__ float g_G1[NLAT*M2*EDIM];
__device__ float g_G2[NLAT*M2*EDIM];
__device__ float g_cA[LMAXD*MMAXD*2*EDIM];
__device__ float g_cB[LMAXD*MMAXD*2*EDIM];
__device__ float g_stats[2*EDIM];
__device__ float g_murs[2*EDIM];

__device__ __forceinline__ float gelu_f(float x){
    return 0.5f*x*(1.0f+erff(x*0.7071067811865475f));
}

// ---------------- setup kernels ----------------
__global__ void legendre_k(float* __restrict__ Pw, float* __restrict__ Pinv, int T){
    int t = blockIdx.x*blockDim.x + threadIdx.x;
    if (t >= T) return;
    double theta = M_PI*((double)t + 0.5)/(double)T;
    double ct = cos(theta), st = sin(theta);
    double w = (M_PI/(double)T)*st;
    double diag = sqrt(1.0/(4.0*M_PI));
    for (int m = 0; m < MMAXD; m++){
        if (m > 0){
            if (m < LMAXD) diag = sqrt((2.0*m+1.0)/(2.0*m))*st*diag;
            else diag = 0.0;
        }
        double pl1 = 0.0, pl2 = 0.0;
        for (int l = 0; l < LMAXD; l++){
            double v;
            if (m >= LMAXD || l < m) v = 0.0;
            else if (l == m) v = diag;
            else if (l == m+1) v = sqrt(2.0*m+3.0)*ct*diag;
            else {
                double dl = (double)l, dm = (double)m;
                double a = sqrt((4.0*dl*dl-1.0)/(dl*dl-dm*dm));
                double b = sqrt(((dl-1.0)*(dl-1.0)-dm*dm)/(4.0*(dl-1.0)*(dl-1.0)-1.0));
                v = a*(ct*pl1 - b*pl2);
            }
            pl2 = pl1; pl1 = v;
            Pw[((long long)l*MMAXD + m)*T + t]   = (float)(v*w);
            Pinv[((long long)m*T + t)*LMAXD + l] = (float)v;
        }
    }
}

__global__ void fft_tables_k(float* __restrict__ Tf, float* __restrict__ Ti, int n){
    int idx = blockIdx.x*blockDim.x + threadIdx.x;
    if (idx >= MMAXD*n) return;
    int m = idx / n, j = idx % n;
    double ang = (2.0*M_PI*(double)m*(double)j)/(double)n;
    double s, c;
    sincos(ang, &s, &c);
    double sc = 2.0*M_PI/(double)n;
    Tf[(2*m)*n + j]   = (float)(c*sc);
    Tf[(2*m+1)*n + j] = (float)(-s*sc);
    bool nyq = (2*m == n);
    double am = (m == 0 || nyq) ? 1.0 : 2.0;
    Ti[(long long)j*M2 + 2*m]   = (float)(am*c);
    Ti[(long long)j*M2 + 2*m+1] = (m == 0 || nyq) ? 0.0f : (float)(-2.0*s);
}

__global__ void transpose_k(const float* __restrict__ in, float* __restrict__ out, int R, int C){
    long long idx = (long long)blockIdx.x*blockDim.x + threadIdx.x;
    if (idx >= (long long)R*C) return;
    int c = (int)(idx % C);
    long long r = idx / C;
    out[(long long)c*R + r] = in[idx];
}

__global__ void build_wbig_k(const float* __restrict__ wr, const float* __restrict__ wi,
                             float* __restrict__ W){
    long long idx = (long long)blockIdx.x*blockDim.x + threadIdx.x;
    if (idx >= (long long)NBLK*EDIM*EDIM*LMAXD) return;
    int l = (int)(idx % LMAXD); long long r = idx / LMAXD;
    int i = (int)(r % EDIM); r /= EDIM;
    int o = (int)(r % EDIM); int b = (int)(r / EDIM);
    float vr = wr[idx], vi = wi[idx];   // layout [b][o][i][l]
    float* M = W + ((long long)b*LMAXD + l)*65536;
    M[(long long)i*256 + o]             = vr;
    M[(long long)i*256 + 128 + o]       = vi;
    M[(long long)(128+i)*256 + o]       = -vi;
    M[(long long)(128+i)*256 + 128 + o] = vr;
}

__global__ void concat_k(const float* __restrict__ xe, const float* __restrict__ xin,
                         float* __restrict__ out){
    long long idx = (long long)blockIdx.x*blockDim.x + threadIdx.x;
    if (idx >= (long long)PFULL*(EDIM+CINCH)) return;
    long long p = idx / (EDIM+CINCH);
    int c = (int)(idx % (EDIM+CINCH));
    out[idx] = (c < EDIM) ? xe[p*EDIM + c] : xin[p*CINCH + (c-EDIM)];
}

__global__ void zero_k(float* p, int n){
    int i = blockIdx.x*blockDim.x + threadIdx.x;
    if (i < n) p[i] = 0.0f;
}

// ---------------- instance norm ----------------
__global__ void inorm_reduce_k(const float* __restrict__ x, int P, float* __restrict__ stats){
    int ch = threadIdx.x;
    float s = 0.f, q = 0.f;
    for (int r = blockIdx.x; r < P; r += gridDim.x){
        float v = x[(long long)r*EDIM + ch];
        s += v; q += v*v;
    }
    atomicAdd(&stats[ch], s);
    atomicAdd(&stats[EDIM+ch], q);
}
__global__ void inorm_fin_k(const float* __restrict__ stats, float* __restrict__ murs, float invP){
    int ch = threadIdx.x;
    float mu = stats[ch]*invP;
    float var = stats[EDIM+ch]*invP - mu*mu;
    murs[ch] = mu;
    murs[EDIM+ch] = rsqrtf(var + 1e-6f);
}
__global__ void inorm_apply_k(const float* __restrict__ x, float* __restrict__ y,
                              const float* __restrict__ murs,
                              const float* __restrict__ g, const float* __restrict__ b,
                              long long total, int act){
    long long idx = (long long)blockIdx.x*blockDim.x + threadIdx.x;
    if (idx >= total) return;
    int ch = (int)(idx & (EDIM-1));
    float v = (x[idx] - murs[ch])*murs[EDIM+ch]*g[ch] + b[ch];
    if (act) v = gelu_f(v);
    y[idx] = v;
}

// ---------------- generic batched GEMM: 128x128x16, double-buffered, 8x8 micro ----------------
// C = act(A@B + bias) + add ; row-major with lda/ldb/ldc, per-batch element strides.
#define BM 128
#define BN 128
#define BKK 16

__global__ __launch_bounds__(256, 2)
void gemm_k(const float* __restrict__ A, const float* __restrict__ B,
            float* __restrict__ C,
            const float* __restrict__ bias, const float* __restrict__ addp,
            int M, int N, int K, int lda, int ldb, int ldc,
            long long sA, long long sB, long long sC, int act){
    __shared__ float As[2][BKK][BM+4];   // padded to kill STS bank conflicts
    __shared__ float Bs[2][BKK][BN];

    long long z = blockIdx.z;
    A += z*sA; B += z*sB; C += z*sC;
    if (addp) addp += z*sC;
    int m0 = blockIdx.y*BM, n0 = blockIdx.x*BN;
    int tid = threadIdx.x;

    // load mappings
    int a_m = tid >> 1;               // 0..127
    int a_k = (tid & 1) * 8;          // 0 or 8 (8 consecutive k each)
    // B: idx = tid + 256*s -> k = idx>>7, n = idx&127

    // compute mapping
    int ty = tid >> 4;                // 0..15 -> rows ty*8..ty*8+7
    int tx = tid & 15;                // 0..15 -> cols tx*8..tx*8+7

    float acc[8][8] = {};
    float ra[8], rb[8];

    // prologue: load tile 0 into buffer 0
    {
        const int k0 = 0;
        #pragma unroll
        for (int s = 0; s < 8; s++){
            int m = m0 + a_m, k = k0 + a_k + s;
            As[0][a_k+s][a_m] = (m < M && k < K) ? A[(long long)m*lda + k] : 0.f;
        }
        #pragma unroll
        for (int s = 0; s < 8; s++){
            int idx = tid + 256*s;
            int k = idx >> 7, n = idx & 127;
            int kk = k0 + k, nn = n0 + n;
            Bs[0][k][n] = (kk < K && nn < N) ? B[(long long)kk*ldb + nn] : 0.f;
        }
    }
    __syncthreads();

    int buf = 0;
    for (int k0 = 0; k0 < K; k0 += BKK){
        int kn = k0 + BKK;
        // prefetch next tile into registers
        if (kn < K){
            #pragma unroll
            for (int s = 0; s < 8; s++){
                int m = m0 + a_m, k = kn + a_k + s;
                ra[s] = (m < M && k < K) ? A[(long long)m*lda + k] : 0.f;
            }
            #pragma unroll
            for (int s = 0; s < 8; s++){
                int idx = tid + 256*s;
                int k = idx >> 7, n = idx & 127;
                int kk = kn + k, nn = n0 + n;
                rb[s] = (kk < K && nn < N) ? B[(long long)kk*ldb + nn] : 0.f;
            }
        }
        // compute on current buffer
        #pragma unroll
        for (int k = 0; k < BKK; k++){
            float4 a0 = *(const float4*)&As[buf][k][ty*8];
            float4 a1 = *(const float4*)&As[buf][k][ty*8+4];
            float4 b0 = *(const float4*)&Bs[buf][k][tx*8];
            float4 b1 = *(const float4*)&Bs[buf][k][tx*8+4];
            float av[8] = {a0.x,a0.y,a0.z,a0.w,a1.x,a1.y,a1.z,a1.w};
            float bv[8] = {b0.x,b0.y,b0.z,b0.w,b1.x,b1.y,b1.z,b1.w};
            #pragma unroll
            for (int r = 0; r < 8; r++)
                #pragma unroll
                for (int c = 0; c < 8; c++)
                    acc[r][c] += av[r]*bv[c];
        }
        // store prefetched tile into other buffer
        if (kn < K){
            int nb = buf ^ 1;
            #pragma unroll
            for (int s = 0; s < 8; s++)
                As[nb][a_k+s][a_m] = ra[s];
            #pragma unroll
            for (int s = 0; s < 8; s++){
                int idx = tid + 256*s;
                Bs[nb][idx>>7][idx&127] = rb[s];
            }
        }
        __syncthreads();
        buf ^= 1;
    }

    // epilogue
    #pragma unroll
    for (int r = 0; r < 8; r++){
        int m = m0 + ty*8 + r; if (m >= M) continue;
        #pragma unroll
        for (int c = 0; c < 8; c++){
            int n = n0 + tx*8 + c; if (n >= N) continue;
            float v = acc[r][c];
            if (bias) v += bias[n];
            if (act == 1) v = gelu_f(v);
            if (addp) v += addp[(long long)m*ldc + n];
            C[(long long)m*ldc + n] = v;
        }
    }
}

// ---------------- host helpers ----------------
static void launch_gemm(const float* A, const float* B, float* C,
                        const float* bias, const float* addp,
                        int M, int N, int K, int lda, int ldb, int ldc,
                        long long sA, long long sB, long long sC, int batch, int act){
    dim3 grid((N+BN-1)/BN, (M+BM-1)/BM, batch);
    gemm_k<<<grid, 256>>>(A, B, C, bias, addp, M, N, K, lda, ldb, ldc, sA, sB, sC, act);
}

#define SYMP(var, sym) do { void* _t = nullptr; cudaGetSymbolAddress(&_t, sym); var = (float*)_t; } while(0)

static void inorm_seq(const float* x, float* y, const float* g, const float* b,
                      int P, int act, float* stats, float* murs){
    zero_k<<<1, 256>>>(stats, 2*EDIM);
    inorm_reduce_k<<<256, EDIM>>>(x, P, stats);
    inorm_fin_k<<<1, EDIM>>>(stats, murs, 1.0f/(float)P);
    long long tot = (long long)P*EDIM;
    inorm_apply_k<<<(unsigned)((tot+255)/256), 256>>>(x, y, murs, g, b, tot, act);
}

extern "C" void kernel_launch(void* const* d_in, const int* in_sizes, int n_in,
                              void* d_out, int out_size){
    const float* x_in    = (const float*)d_in[0];
    const float* w_enc0  = (const float*)d_in[1];
    const float* b_enc0  = (const float*)d_in[2];
    const float* w_enc1  = (const float*)d_in[3];
    const float* w_specr = (const float*)d_in[4];
    const float* w_speci = (const float*)d_in[5];
    const float* g0      = (const float*)d_in[6];
    const float* b0      = (const float*)d_in[7];
    const float* g1      = (const float*)d_in[8];
    const float* b1      = (const float*)d_in[9];
    const float* w_mlp1  = (const float*)d_in[10];
    const float* b_mlp1  = (const float*)d_in[11];
    const float* w_mlp2  = (const float*)d_in[12];
    const float* b_mlp2  = (const float*)d_in[13];
    const float* w_skip  = (const float*)d_in[14];
    const float* w_dec0  = (const float*)d_in[15];
    const float* b_dec0  = (const float*)d_in[16];
    const float* w_dec1  = (const float*)d_in[17];
    float* out = (float*)d_out;

    float *Pwf,*Pif,*Pws,*Pis,*Tff,*Tif,*Tfs,*Tis,*Wbig;
    float *wTe0,*wTe1,*wTm1,*wTm2,*wTsk,*wTd0,*wTd1;
    float *xin,*bufA,*bufB,*bufC,*bufD,*bufE,*bufH,*G1,*G2,*cA,*cB,*stats,*murs;
    SYMP(Pwf, g_Pw_full);  SYMP(Pif, g_Pinv_full);
    SYMP(Pws, g_Pw_small); SYMP(Pis, g_Pinv_small);
    SYMP(Tff, g_Tf_full);  SYMP(Tif, g_Ti_full);
    SYMP(Tfs, g_Tf_small); SYMP(Tis, g_Ti_small);
    SYMP(Wbig, g_Wbig);
    SYMP(wTe0, g_wT_enc0); SYMP(wTe1, g_wT_enc1);
    SYMP(wTm1, g_wT_mlp1); SYMP(wTm2, g_wT_mlp2); SYMP(wTsk, g_wT_skip);
    SYMP(wTd0, g_wT_dec0); SYMP(wTd1, g_wT_dec1);
    SYMP(xin, g_xin);
    SYMP(bufA, g_bufA); SYMP(bufB, g_bufB); SYMP(bufC, g_bufC);
    SYMP(bufD, g_bufD); SYMP(bufE, g_bufE); SYMP(bufH, g_bufH);
    SYMP(G1, g_G1); SYMP(G2, g_G2); SYMP(cA, g_cA); SYMP(cB, g_cB);
    SYMP(stats, g_stats); SYMP(murs, g_murs);

    // ---- setup: tables + weight transposes (cheap, in-graph) ----
    legendre_k<<<(NLAT+63)/64, 64>>>(Pwf, Pif, NLAT);
    legendre_k<<<(TSM+63)/64, 64>>>(Pws, Pis, TSM);
    fft_tables_k<<<(MMAXD*NLONF+255)/256, 256>>>(Tff, Tif, NLONF);
    fft_tables_k<<<(MMAXD*NLONS+255)/256, 256>>>(Tfs, Tis, NLONS);
    transpose_k<<<(EDIM*CINCH+255)/256, 256>>>(w_enc0, wTe0, EDIM, CINCH);
    transpose_k<<<(EDIM*EDIM+255)/256, 256>>>(w_enc1, wTe1, EDIM, EDIM);
    for (int i = 0; i < NBLK; i++){
        transpose_k<<<(HID*EDIM+255)/256, 256>>>(w_mlp1 + (long long)i*HID*EDIM, wTm1 + (long long)i*EDIM*HID, HID, EDIM);
        transpose_k<<<(EDIM*HID+255)/256, 256>>>(w_mlp2 + (long long)i*EDIM*HID, wTm2 + (long long)i*HID*EDIM, EDIM, HID);
        transpose_k<<<(EDIM*EDIM+255)/256, 256>>>(w_skip + (long long)i*EDIM*EDIM, wTsk + (long long)i*EDIM*EDIM, EDIM, EDIM);
    }
    transpose_k<<<(EDIM*(EDIM+CINCH)+255)/256, 256>>>(w_dec0, wTd0, EDIM, EDIM+CINCH);
    transpose_k<<<(COUTCH*EDIM+255)/256, 256>>>(w_dec1, wTd1, COUTCH, EDIM);
    build_wbig_k<<<(unsigned)(((long long)NBLK*EDIM*EDIM*LMAXD + 255)/256), 256>>>(w_specr, w_speci, Wbig);
    transpose_k<<<(unsigned)(((long long)CINCH*PFULL + 255)/256), 256>>>(x_in, xin, CINCH, PFULL);

    // ---- encoder: bufA = enc1 @ gelu(enc0 @ x + b) ----
    launch_gemm(xin,  wTe0, bufC, b_enc0, nullptr, PFULL, EDIM, CINCH, CINCH, EDIM, EDIM, 0,0,0, 1, 1);
    launch_gemm(bufC, wTe1, bufA, nullptr, nullptr, PFULL, EDIM, EDIM, EDIM, EDIM, EDIM, 0,0,0, 1, 0);

    // ---- blocks ----
    struct Blk { int Tin, nlin, Tout, nlout; bool sres; };
    const Blk blks[NBLK] = {
        {NLAT, NLONF, TSM, NLONS, true},
        {TSM, NLONS, TSM, NLONS, false},
        {TSM, NLONS, TSM, NLONS, false},
        {TSM, NLONS, NLAT, NLONF, true},
    };
    float* infld[NBLK]  = {bufA, bufA, bufE, bufA};
    float* outfld[NBLK] = {bufA, bufE, bufA, bufB};

    for (int i = 0; i < NBLK; i++){
        const Blk& bk = blks[i];
        const float* Tf_in  = (bk.nlin == NLONF) ? Tff : Tfs;
        const float* Pw_in  = (bk.Tin == NLAT) ? Pwf : Pws;
        const float* Pi_out = (bk.Tout == NLAT) ? Pif : Pis;
        const float* Ti_out = (bk.nlout == NLONF) ? Tif : Tis;
        int Pout = bk.Tout * bk.nlout;
        float* in = infld[i];
        float* xout = outfld[i];

        // forward rFFT: G1[t][m2][ch] (batch over t)
        launch_gemm(Tf_in, in, G1, nullptr, nullptr,
                    M2, EDIM, bk.nlin, bk.nlin, EDIM, EDIM,
                    0, (long long)bk.nlin*EDIM, (long long)M2*EDIM, bk.Tin, 0);
        // Legendre analysis: cA[l][m2][ch] (batch over m)
        launch_gemm(Pw_in, G1, cA, nullptr, nullptr,
                    LMAXD, 256, bk.Tin, MMAXD*bk.Tin, M2*EDIM, MMAXD*256,
                    bk.Tin, 256, 256, MMAXD, 0);
        // spectral conv (batch over l): cB = cA @ Wbig_l
        launch_gemm(cA, Wbig + (long long)i*LMAXD*65536, cB, nullptr, nullptr,
                    MMAXD, 256, 256, 256, 256, 256,
                    (long long)MMAXD*256, 65536, (long long)MMAXD*256, LMAXD, 0);
        // Legendre synthesis (spec path): G1[t][m2][ch] (batch over m)
        launch_gemm(Pi_out, cB, G1, nullptr, nullptr,
                    bk.Tout, 256, LMAXD, LMAXD, MMAXD*256, M2*EDIM,
                    (long long)bk.Tout*LMAXD, 256, 256, MMAXD, 0);
        // inverse rFFT: xf -> bufB (batch over t)
        launch_gemm(Ti_out, G1, bufB, nullptr, nullptr,
                    bk.nlout, EDIM, M2, M2, EDIM, EDIM,
                    0, (long long)M2*EDIM, (long long)bk.nlout*EDIM, bk.Tout, 0);

        // residual
        const float* res;
        if (bk.sres){
            launch_gemm(Pi_out, cA, G2, nullptr, nullptr,
                        bk.Tout, 256, LMAXD, LMAXD, MMAXD*256, M2*EDIM,
                        (long long)bk.Tout*LMAXD, 256, 256, MMAXD, 0);
            launch_gemm(Ti_out, G2, bufC, nullptr, nullptr,
                        bk.nlout, EDIM, M2, M2, EDIM, EDIM,
                        0, (long long)M2*EDIM, (long long)bk.nlout*EDIM, bk.Tout, 0);
            res = bufC;
        } else {
            res = in;
        }

        // norm0 + gelu -> bufD
        inorm_seq(bufB, bufD, g0 + (long long)i*EDIM, b0 + (long long)i*EDIM, Pout, 1, stats, murs);
        // MLP: bufH = gelu(bufD @ W1 + b1) ; bufB = bufH @ W2 + b2
        launch_gemm(bufD, wTm1 + (long long)i*EDIM*HID, bufH, b_mlp1 + (long long)i*HID, nullptr,
                    Pout, HID, EDIM, EDIM, HID, HID, 0,0,0, 1, 1);
        launch_gemm(bufH, wTm2 + (long long)i*HID*EDIM, bufB, b_mlp2 + (long long)i*EDIM, nullptr,
                    Pout, EDIM, HID, HID, EDIM, EDIM, 0,0,0, 1, 0);
        // norm1 -> bufD
        inorm_seq(bufB, bufD, g1 + (long long)i*EDIM, b1 + (long long)i*EDIM, Pout, 0, stats, murs);
        // x_next = bufD + res @ w_skip
        launch_gemm(res, wTsk + (long long)i*EDIM*EDIM, xout, nullptr, bufD,
                    Pout, EDIM, EDIM, EDIM, EDIM, EDIM, 0,0,0, 1, 0);
    }

    // ---- decoder ----
    concat_k<<<(unsigned)(((long long)PFULL*(EDIM+CINCH) + 255)/256), 256>>>(bufB, xin, bufH);
    launch_gemm(bufH, wTd0, bufA, b_dec0, nullptr,
                PFULL, EDIM, EDIM+CINCH, EDIM+CINCH, EDIM, EDIM, 0,0,0, 1, 1);
    launch_gemm(bufA, wTd1, bufC, nullptr, nullptr,
                PFULL, COUTCH, EDIM, EDIM, COUTCH, COUTCH, 0,0,0, 1, 0);
    // [P][26] -> [26][P]
    transpose_k<<<(unsigned)(((long long)PFULL*COUTCH + 255)/256), 256>>>(bufC, out, PFULL, COUTCH);
}